// round 3
// baseline (speedup 1.0000x reference)
#include <cuda_runtime.h>

// Problem constants (match reference)
#define B_ 8
#define S_ 2048
#define N_ 512
#define D_ 1024
#define MAX_W_ 32
#define MASK_FILL_ (-1000.0f)

// Scratch for global attention logits (B*S floats = 64 KB).
__device__ float g_logits[B_ * S_];

// Kernel 1: logits[b,s] = dot(seq[b,s,:], att_w) + att_b
__global__ void __launch_bounds__(256)
logits_kernel(const float* __restrict__ seq,
              const float* __restrict__ att_w,
              const float* __restrict__ att_b) {
    int warp = (blockIdx.x * blockDim.x + threadIdx.x) >> 5;
    int lane = threadIdx.x & 31;
    if (warp >= B_ * S_) return;

    const float4* row = reinterpret_cast<const float4*>(seq + (size_t)warp * D_);
    const float4* w4  = reinterpret_cast<const float4*>(att_w);

    float acc = 0.0f;
    #pragma unroll
    for (int i = 0; i < (D_ / 4) / 32; i++) {   // 8 iterations
        float4 a = row[lane + i * 32];
        float4 w = w4[lane + i * 32];
        acc += a.x * w.x + a.y * w.y + a.z * w.z + a.w * w.w;
    }
    #pragma unroll
    for (int off = 16; off; off >>= 1)
        acc += __shfl_xor_sync(0xffffffffu, acc, off);

    if (lane == 0)
        g_logits[warp] = acc + att_b[0];
}

// Kernel 2: one WARP per (span, half-row). Fully warp-autonomous:
//   - each warp computes the span softmax itself (lane t <-> position t,
//     walking backward from `end`; masked lanes contribute exp = 0, identical
//     arithmetic to the reference since exp(-1000 - mx) underflows to 0).
//   - each lane owns 4 float4 columns of its half-row; rows unrolled x2
//     -> 8 independent LDG.128 in flight per lane, 4 acc chains.
//   - weight for ascending row j is held by lane (width - j); broadcast
//     via dynamic shuffle.
// No shared memory, no __syncthreads.
__global__ void __launch_bounds__(256)
span_kernel(const float* __restrict__ seq,
            const int*   __restrict__ spans,
            float*       __restrict__ out) {
    const int gwarp   = blockIdx.x * (blockDim.x >> 5) + (threadIdx.x >> 5);
    const int lane    = threadIdx.x & 31;
    const int span_id = gwarp >> 1;      // 0 .. B*N-1
    const int half    = gwarp & 1;       // which 2KB half of the row
    const int b       = span_id / N_;

    const int start = spans[span_id * 2 + 0];
    const int end   = spans[span_id * 2 + 1];     // inclusive
    const int width = end - start;                // 0..31
    const bool m    = (lane <= width);

    // --- per-warp softmax over the 32 candidate positions ---
    float logit = m ? g_logits[b * S_ + end - lane] : MASK_FILL_;
    float mx = logit;
    #pragma unroll
    for (int off = 16; off; off >>= 1)
        mx = fmaxf(mx, __shfl_xor_sync(0xffffffffu, mx, off));
    float e = m ? __expf(logit - mx) : 0.0f;
    float sum = e;
    #pragma unroll
    for (int off = 16; off; off >>= 1)
        sum += __shfl_xor_sync(0xffffffffu, sum, off);
    const float myattn = e / sum;   // weight of row (start + width - lane)

    // --- weighted pooling over the valid rows [start .. end] ---
    // lane owns float4 columns: half*128 + k*32 + lane, k = 0..3
    const float4* base = reinterpret_cast<const float4*>(seq)
                       + ((size_t)b * S_ + start) * (D_ / 4)
                       + half * 128 + lane;
    const int R = D_ / 4;   // float4 stride between rows

    float4 a0 = make_float4(0.f,0.f,0.f,0.f);
    float4 a1 = make_float4(0.f,0.f,0.f,0.f);
    float4 a2 = make_float4(0.f,0.f,0.f,0.f);
    float4 a3 = make_float4(0.f,0.f,0.f,0.f);

    const int nv = width + 1;
    int j = 0;
    for (; j + 2 <= nv; j += 2) {
        const float wa = __shfl_sync(0xffffffffu, myattn, width - j);
        const float wb = __shfl_sync(0xffffffffu, myattn, width - j - 1);
        const float4* p = base + (size_t)j * R;
        const float4* q = base + (size_t)(j + 1) * R;
        float4 v0 = p[0],  v1 = p[32],  v2 = p[64],  v3 = p[96];
        float4 u0 = q[0],  u1 = q[32],  u2 = q[64],  u3 = q[96];
        a0.x += wa*v0.x; a0.y += wa*v0.y; a0.z += wa*v0.z; a0.w += wa*v0.w;
        a1.x += wa*v1.x; a1.y += wa*v1.y; a1.z += wa*v1.z; a1.w += wa*v1.w;
        a2.x += wa*v2.x; a2.y += wa*v2.y; a2.z += wa*v2.z; a2.w += wa*v2.w;
        a3.x += wa*v3.x; a3.y += wa*v3.y; a3.z += wa*v3.z; a3.w += wa*v3.w;
        a0.x += wb*u0.x; a0.y += wb*u0.y; a0.z += wb*u0.z; a0.w += wb*u0.w;
        a1.x += wb*u1.x; a1.y += wb*u1.y; a1.z += wb*u1.z; a1.w += wb*u1.w;
        a2.x += wb*u2.x; a2.y += wb*u2.y; a2.z += wb*u2.z; a2.w += wb*u2.w;
        a3.x += wb*u3.x; a3.y += wb*u3.y; a3.z += wb*u3.z; a3.w += wb*u3.w;
    }
    if (j < nv) {
        const float wa = __shfl_sync(0xffffffffu, myattn, width - j);
        const float4* p = base + (size_t)j * R;
        float4 v0 = p[0],  v1 = p[32],  v2 = p[64],  v3 = p[96];
        a0.x += wa*v0.x; a0.y += wa*v0.y; a0.z += wa*v0.z; a0.w += wa*v0.w;
        a1.x += wa*v1.x; a1.y += wa*v1.y; a1.z += wa*v1.z; a1.w += wa*v1.w;
        a2.x += wa*v2.x; a2.y += wa*v2.y; a2.z += wa*v2.z; a2.w += wa*v2.w;
        a3.x += wa*v3.x; a3.y += wa*v3.y; a3.z += wa*v3.z; a3.w += wa*v3.w;
    }

    float4* o = reinterpret_cast<float4*>(out)
              + (size_t)span_id * (D_ / 4) + half * 128 + lane;
    o[0]  = a0;
    o[32] = a1;
    o[64] = a2;
    o[96] = a3;
}

extern "C" void kernel_launch(void* const* d_in, const int* in_sizes, int n_in,
                              void* d_out, int out_size) {
    const float* seq   = (const float*)d_in[0];   // (B, S, D) f32
    const int*   spans = (const int*)  d_in[1];   // (B, N, 2) i32
    const float* att_w = (const float*)d_in[2];   // (D, 1) f32
    const float* att_b = (const float*)d_in[3];   // (1,) f32
    float* out = (float*)d_out;                   // (B, N, D) f32

    logits_kernel<<<(B_ * S_) / 8, 256>>>(seq, att_w, att_b);
    // 2 warps per span, 8 warps per CTA -> B*N*2/8 = 2048 CTAs
    span_kernel<<<(B_ * N_ * 2) / 8, 256>>>(seq, spans, out);
}